// round 10
// baseline (speedup 1.0000x reference)
#include <cuda_runtime.h>
#include <cuda_bf16.h>
#include <cuda_fp16.h>
#include <cstdint>
#include <math.h>

#define SEQ   2048
#define HD    64
#define BM    128
#define BN    64
#define NT    (SEQ / BN)        // 32 k-tiles
#define LOG2E 1.4426950408889634f

// ---- main-kernel smem layout (bytes) ----
#define SQHI   0                // 16 KB Q hi
#define SQLO   16384            // 16 KB Q lo
#define STAGE0 32768
#define STAGEB 40960            // 40 KB per stage
#define OKH    0                // K hi   8 KB
#define OKL    8192             // K lo   8 KB
#define OV     16384            // V fp16 8 KB
#define OM     24576            // mask fp16 16 KB
#define SMEM_TOTAL (STAGE0 + 2 * STAGEB)   // 112 KB

// ---- pre-converted operand images (swizzled tile layout) ----
__device__ uint2 g_KH[64 * NT * 1024];   // 16.8 MB  (8 KB per (bh,kt) tile)
__device__ uint2 g_KL[64 * NT * 1024];   // 16.8 MB
__device__ uint2 g_Vc[64 * NT * 1024];   // 16.8 MB
__device__ uint2 g_Mc[16 * NT * 2048];   // 8.4 MB   (16 KB per (qt,kt) tile)

__device__ __forceinline__ uint32_t sw(uint32_t o) { return o ^ ((o >> 3) & 0x70); }

__device__ __forceinline__ uint32_t smem_u32(const void* p) {
    uint32_t a;
    asm("{ .reg .u64 t; cvta.to.shared.u64 t, %1; cvt.u32.u64 %0, t; }" : "=r"(a) : "l"(p));
    return a;
}
__device__ __forceinline__ void cp16(uint32_t dst, const void* src) {
    asm volatile("cp.async.ca.shared.global [%0], [%1], 16;" :: "r"(dst), "l"(src));
}
__device__ __forceinline__ void ldsm4(uint32_t r[4], uint32_t a) {
    asm volatile("ldmatrix.sync.aligned.m8n8.x4.shared.b16 {%0,%1,%2,%3}, [%4];"
                 : "=r"(r[0]), "=r"(r[1]), "=r"(r[2]), "=r"(r[3]) : "r"(a));
}
__device__ __forceinline__ void ldsm4t(uint32_t r[4], uint32_t a) {
    asm volatile("ldmatrix.sync.aligned.m8n8.x4.trans.shared.b16 {%0,%1,%2,%3}, [%4];"
                 : "=r"(r[0]), "=r"(r[1]), "=r"(r[2]), "=r"(r[3]) : "r"(a));
}
__device__ __forceinline__ void mma_bf16(float d[4], const uint32_t a[4], const uint32_t b[2]) {
    asm volatile("mma.sync.aligned.m16n8k16.row.col.f32.bf16.bf16.f32 "
                 "{%0,%1,%2,%3}, {%4,%5,%6,%7}, {%8,%9}, {%0,%1,%2,%3};"
                 : "+f"(d[0]), "+f"(d[1]), "+f"(d[2]), "+f"(d[3])
                 : "r"(a[0]), "r"(a[1]), "r"(a[2]), "r"(a[3]), "r"(b[0]), "r"(b[1]));
}
__device__ __forceinline__ void mma_fp16(float d[4], const uint32_t a[4], const uint32_t b[2]) {
    asm volatile("mma.sync.aligned.m16n8k16.row.col.f32.f16.f16.f32 "
                 "{%0,%1,%2,%3}, {%4,%5,%6,%7}, {%8,%9}, {%0,%1,%2,%3};"
                 : "+f"(d[0]), "+f"(d[1]), "+f"(d[2]), "+f"(d[3])
                 : "r"(a[0]), "r"(a[1]), "r"(a[2]), "r"(a[3]), "r"(b[0]), "r"(b[1]));
}
__device__ __forceinline__ uint32_t pkbf(float x, float y) {
    uint32_t r;
    asm("cvt.rn.bf16x2.f32 %0, %1, %2;" : "=r"(r) : "f"(y), "f"(x));
    return r;
}
__device__ __forceinline__ uint32_t pk16(float x, float y) {
    uint32_t r;
    asm("cvt.rn.f16x2.f32 %0, %1, %2;" : "=r"(r) : "f"(y), "f"(x));
    return r;
}
__device__ __forceinline__ uint32_t hi2(float x, float y) {
    return __byte_perm(__float_as_uint(x), __float_as_uint(y), 0x7632);
}
__device__ __forceinline__ float hif(float x) {
    return __uint_as_float(__float_as_uint(x) & 0xffff0000u);
}
__device__ __forceinline__ float ex2(float x) {
    float y;
    asm("ex2.approx.ftz.f32 %0, %1;" : "=f"(y) : "f"(x));
    return y;
}

// ================= prologue: convert K/V/mask into swizzled tile images ==========
#define KV_ELEMS (64 * NT * 1024)
#define M_ELEMS  (16 * NT * 2048)

__global__ __launch_bounds__(256)
void prep_kernel(const float* __restrict__ K, const float* __restrict__ V,
                 const float* __restrict__ Mk)
{
    int idx = blockIdx.x * 256 + threadIdx.x;
    if (idx < KV_ELEMS) {
        int d8   = idx & 1023;          // uint2 slot in 8KB tile image
        int tile = idx >> 10;           // bh*NT + kt
        int bh = tile >> 5, kt = tile & 31;
        uint32_t u = sw((uint32_t)d8 * 8);
        int row = u >> 7;               // 0..63 (tile row)
        int c4  = (u & 127) >> 3;       // 0..15 (float4 group)
        size_t srcoff = ((size_t)bh * SEQ + (size_t)kt * BN + row) * HD + c4 * 4;
        float4 kv = *(const float4*)(K + srcoff);
        float4 vv = *(const float4*)(V + srcoff);
        g_KH[idx] = make_uint2(hi2(kv.x, kv.y), hi2(kv.z, kv.w));
        g_KL[idx] = make_uint2(pkbf(kv.x - hif(kv.x), kv.y - hif(kv.y)),
                               pkbf(kv.z - hif(kv.z), kv.w - hif(kv.w)));
        g_Vc[idx] = make_uint2(pk16(vv.x, vv.y), pk16(vv.z, vv.w));
    } else if (idx < KV_ELEMS + M_ELEMS) {
        int j    = idx - KV_ELEMS;
        int d8   = j & 2047;            // uint2 slot in 16KB tile image
        int tile = j >> 11;             // qt*NT + kt
        int qt = tile >> 5, kt = tile & 31;
        uint32_t u = sw((uint32_t)d8 * 8);
        int qrow = u >> 7;              // 0..127
        int c4   = (u & 127) >> 1;      // fp16 col base (multiple of 4)
        const float4 mv = *(const float4*)(Mk + (size_t)(qt * BM + qrow) * SEQ + kt * BN + c4);
        g_Mc[j] = make_uint2(pk16(mv.x, mv.y), pk16(mv.z, mv.w));
    }
}

// ================= main kernel ===================================================

__device__ __forceinline__ void issue_tile(uint32_t dstb, int tid,
                                           const char* sKH, const char* sKL,
                                           const char* sV, const char* sM)
{
    #pragma unroll
    for (int c = 0; c < 10; c++) {
        int byte = (c * 256 + tid) * 16;   // per-c: uniform 4KB region
        const char* src;
        if      (byte < 8192)  src = sKH + byte;
        else if (byte < 16384) src = sKL + (byte - 8192);
        else if (byte < 24576) src = sV  + (byte - 16384);
        else                   src = sM  + (byte - 24576);
        cp16(dstb + byte, src);
    }
    asm volatile("cp.async.commit_group;" ::: "memory");
}

__global__ __launch_bounds__(256, 2)
void flash_mma_kernel(const float* __restrict__ Q, float* __restrict__ O)
{
    extern __shared__ char smem[];
    const uint32_t sb = smem_u32(smem);
    const int tid  = threadIdx.x;
    const int lane = tid & 31;
    const int wid  = tid >> 5;          // 0..7, 16 Q rows per warp
    const int bh   = blockIdx.y;
    const int qt   = blockIdx.x;

    const float* Qb = Q + ((size_t)bh * SEQ + (size_t)qt * BM) * HD;
    const char* baseKH = (const char*)g_KH + ((size_t)(bh * NT) << 13);
    const char* baseKL = (const char*)g_KL + ((size_t)(bh * NT) << 13);
    const char* baseV  = (const char*)g_Vc + ((size_t)(bh * NT) << 13);
    const char* baseM  = (const char*)g_Mc + ((size_t)(qt * NT) << 14);

    const int g  = lane >> 3;
    const int i8 = lane & 7;

    // ---- issue tile 0 into stage 0 ----
    issue_tile(sb + STAGE0, tid, baseKH, baseKL, baseV, baseM);

    // ---- Load + convert Q tile (hi trunc-bf16 / lo residual) ----
    for (int j = tid; j < BM * 16; j += 256) {
        int row = j >> 4, c = j & 15;
        float4 v = *(const float4*)(Qb + row * HD + c * 4);
        uint32_t o = sw(row * 128 + c * 8);
        *(uint2*)(smem + SQHI + o) = make_uint2(hi2(v.x, v.y), hi2(v.z, v.w));
        *(uint2*)(smem + SQLO + o) =
            make_uint2(pkbf(v.x - hif(v.x), v.y - hif(v.y)),
                       pkbf(v.z - hif(v.z), v.w - hif(v.w)));
    }
    __syncthreads();

    // ---- hoist Q fragments for all 4 k-chunks ----
    uint32_t aQh[4][4], aQl[4][4];
    #pragma unroll
    for (int kc = 0; kc < 4; kc++) {
        uint32_t arow = wid * 16 + (g & 1) * 8 + i8;
        uint32_t acol = kc * 16 + (g >> 1) * 8;
        uint32_t o = sw(arow * 128 + acol * 2);
        ldsm4(aQh[kc], sb + SQHI + o);
        ldsm4(aQl[kc], sb + SQLO + o);
    }

    float Sacc[8][4];
    float Oacc[8][4];
    float mrun0 = -1e30f, mrun1 = -1e30f, lrun0 = 0.0f, lrun1 = 0.0f;
    #pragma unroll
    for (int nt = 0; nt < 8; nt++)
        #pragma unroll
        for (int e = 0; e < 4; e++) Oacc[nt][e] = 0.0f;

    const int r0 = lane >> 2;

    for (int kt = 0; kt < NT; kt++) {
        const uint32_t stg = STAGE0 + (kt & 1) * STAGEB;

        // prefetch next tile into the other stage
        if (kt < NT - 1) {
            size_t t = (size_t)(kt + 1) << 13;
            issue_tile(sb + STAGE0 + ((kt + 1) & 1) * STAGEB, tid,
                       baseKH + t, baseKL + t, baseV + t,
                       baseM + ((size_t)(kt + 1) << 14));
            asm volatile("cp.async.wait_group 1;" ::: "memory");
        } else {
            asm volatile("cp.async.wait_group 0;" ::: "memory");
        }
        __syncthreads();

        // ---- GEMM1: S = Q K^T (3-pass bf16 hi/lo) ----
        #pragma unroll
        for (int nt = 0; nt < 8; nt++)
            #pragma unroll
            for (int e = 0; e < 4; e++) Sacc[nt][e] = 0.0f;

        #pragma unroll
        for (int kc = 0; kc < 4; kc++) {
            #pragma unroll
            for (int nt2 = 0; nt2 < 4; nt2++) {
                uint32_t brow = nt2 * 16 + (g >> 1) * 8 + i8;
                uint32_t bcol = kc * 16 + (g & 1) * 8;
                uint32_t o = sw(brow * 128 + bcol * 2);
                uint32_t bKh[4], bKl[4];
                ldsm4(bKh, sb + stg + OKH + o);
                ldsm4(bKl, sb + stg + OKL + o);
                #pragma unroll
                for (int h = 0; h < 2; h++) {
                    mma_bf16(Sacc[nt2 * 2 + h], aQh[kc], bKh + 2 * h);
                    mma_bf16(Sacc[nt2 * 2 + h], aQh[kc], bKl + 2 * h);
                    mma_bf16(Sacc[nt2 * 2 + h], aQl[kc], bKh + 2 * h);
                }
            }
        }

        // ---- online softmax (mask fp16 from smem image) ----
        {
            const uint32_t mb = sb + stg + OM;
            float mx0 = -1e30f, mx1 = -1e30f;
            #pragma unroll
            for (int nt = 0; nt < 8; nt++) {
                uint32_t col = nt * 16 + (lane & 3) * 4;
                uint32_t raw0 = *(const uint32_t*)(smem + (mb - sb) + sw((wid * 16 + r0) * 128 + col));
                uint32_t raw1 = *(const uint32_t*)(smem + (mb - sb) + sw((wid * 16 + r0 + 8) * 128 + col));
                float2 m0 = __half22float2(*(const __half2*)&raw0);
                float2 m1 = __half22float2(*(const __half2*)&raw1);
                Sacc[nt][0] += m0.x;
                Sacc[nt][1] += m0.y;
                Sacc[nt][2] += m1.x;
                Sacc[nt][3] += m1.y;
                mx0 = fmaxf(mx0, fmaxf(Sacc[nt][0], Sacc[nt][1]));
                mx1 = fmaxf(mx1, fmaxf(Sacc[nt][2], Sacc[nt][3]));
            }
            mx0 = fmaxf(mx0, __shfl_xor_sync(0xffffffffu, mx0, 1));
            mx0 = fmaxf(mx0, __shfl_xor_sync(0xffffffffu, mx0, 2));
            mx1 = fmaxf(mx1, __shfl_xor_sync(0xffffffffu, mx1, 1));
            mx1 = fmaxf(mx1, __shfl_xor_sync(0xffffffffu, mx1, 2));

            float mn0 = fmaxf(mrun0, mx0);
            float mn1 = fmaxf(mrun1, mx1);
            float corr0 = ex2((mrun0 - mn0) * LOG2E);
            float corr1 = ex2((mrun1 - mn1) * LOG2E);
            mrun0 = mn0; mrun1 = mn1;

            float s0 = 0.0f, s1 = 0.0f;
            #pragma unroll
            for (int nt = 0; nt < 8; nt++) {
                float p0 = ex2((Sacc[nt][0] - mn0) * LOG2E);
                float p1 = ex2((Sacc[nt][1] - mn0) * LOG2E);
                float p2 = ex2((Sacc[nt][2] - mn1) * LOG2E);
                float p3 = ex2((Sacc[nt][3] - mn1) * LOG2E);
                s0 += p0 + p1;
                s1 += p2 + p3;
                Sacc[nt][0] = p0; Sacc[nt][1] = p1;
                Sacc[nt][2] = p2; Sacc[nt][3] = p3;
                Oacc[nt][0] *= corr0; Oacc[nt][1] *= corr0;
                Oacc[nt][2] *= corr1; Oacc[nt][3] *= corr1;
            }
            lrun0 = lrun0 * corr0 + s0;
            lrun1 = lrun1 * corr1 + s1;
        }

        // ---- GEMM2: O += P V (single-pass fp16, P from registers) ----
        #pragma unroll
        for (int kc = 0; kc < 4; kc++) {
            uint32_t aP[4];
            {
                const float* t0 = Sacc[2 * kc];
                const float* t1 = Sacc[2 * kc + 1];
                aP[0] = pk16(t0[0], t0[1]);
                aP[1] = pk16(t0[2], t0[3]);
                aP[2] = pk16(t1[0], t1[1]);
                aP[3] = pk16(t1[2], t1[3]);
            }
            #pragma unroll
            for (int nt2 = 0; nt2 < 4; nt2++) {
                uint32_t vrow = kc * 16 + (g & 1) * 8 + i8;
                uint32_t vcol = nt2 * 16 + (g >> 1) * 8;
                uint32_t o = sw(vrow * 128 + vcol * 2);
                uint32_t bV[4];
                ldsm4t(bV, sb + stg + OV + o);
                #pragma unroll
                for (int h = 0; h < 2; h++)
                    mma_fp16(Oacc[nt2 * 2 + h], aP, bV + 2 * h);
            }
        }
        __syncthreads();   // stage fully consumed before it is refilled
    }

    // ---- epilogue ----
    {
        float s0 = lrun0, s1 = lrun1;
        s0 += __shfl_xor_sync(0xffffffffu, s0, 1);
        s0 += __shfl_xor_sync(0xffffffffu, s0, 2);
        s1 += __shfl_xor_sync(0xffffffffu, s1, 1);
        s1 += __shfl_xor_sync(0xffffffffu, s1, 2);
        float inv0 = 1.0f / s0;
        float inv1 = 1.0f / s1;
        int grow = qt * BM + wid * 16 + r0;
        float* o0 = O + ((size_t)bh * SEQ + grow) * HD;
        float* o1 = O + ((size_t)bh * SEQ + grow + 8) * HD;
        #pragma unroll
        for (int nt = 0; nt < 8; nt++) {
            int c = nt * 8 + 2 * (lane & 3);
            *(float2*)(o0 + c) = make_float2(Oacc[nt][0] * inv0, Oacc[nt][1] * inv0);
            *(float2*)(o1 + c) = make_float2(Oacc[nt][2] * inv1, Oacc[nt][3] * inv1);
        }
    }
}

extern "C" void kernel_launch(void* const* d_in, const int* in_sizes, int n_in,
                              void* d_out, int out_size)
{
    const float* Q  = (const float*)d_in[0];
    const float* K  = (const float*)d_in[1];
    const float* V  = (const float*)d_in[2];
    const float* Mk = (const float*)d_in[3];
    float* O = (float*)d_out;

    int bh = in_sizes[0] / (SEQ * HD);   // B*H = 64

    prep_kernel<<<(KV_ELEMS + M_ELEMS) / 256, 256>>>(K, V, Mk);

    cudaFuncSetAttribute(flash_mma_kernel,
                         cudaFuncAttributeMaxDynamicSharedMemorySize, SMEM_TOTAL);
    dim3 grid(SEQ / BM, bh);
    flash_mma_kernel<<<grid, 256, SMEM_TOTAL>>>(Q, O);
}

// round 12
// speedup vs baseline: 1.0009x; 1.0009x over previous
#include <cuda_runtime.h>
#include <cuda_bf16.h>
#include <cuda_fp16.h>
#include <cstdint>
#include <math.h>

#define SEQ   2048
#define HD    64
#define BM    128
#define BN    64
#define NT    (SEQ / BN)        // 32 k-tiles
#define LOG2E 1.4426950408889634f

// ---- main-kernel smem layout (bytes) ----
#define SQHI   0                // 16 KB Q hi
#define SQLO   16384            // 16 KB Q lo
#define STAGE0 32768
#define STAGEB 40960            // 40 KB per stage
#define OKH    0                // K hi   8 KB
#define OKL    8192             // K lo   8 KB
#define OV     16384            // V fp16 8 KB
#define OM     24576            // mask fp16 16 KB
#define SMEM_TOTAL (STAGE0 + 2 * STAGEB)   // 112 KB

// ---- pre-converted operand images (swizzled tile layout) ----
__device__ uint2 g_KH[64 * NT * 1024];   // 16.8 MB  (8 KB per (bh,kt) tile)
__device__ uint2 g_KL[64 * NT * 1024];   // 16.8 MB
__device__ uint2 g_Vc[64 * NT * 1024];   // 16.8 MB
__device__ uint2 g_Mc[16 * NT * 2048];   // 8.4 MB   (16 KB per (qt,kt) tile)

__device__ __forceinline__ uint32_t sw(uint32_t o) { return o ^ ((o >> 3) & 0x70); }

__device__ __forceinline__ uint32_t smem_u32(const void* p) {
    uint32_t a;
    asm("{ .reg .u64 t; cvta.to.shared.u64 t, %1; cvt.u32.u64 %0, t; }" : "=r"(a) : "l"(p));
    return a;
}
__device__ __forceinline__ void cp16(uint32_t dst, const void* src) {
    asm volatile("cp.async.ca.shared.global [%0], [%1], 16;" :: "r"(dst), "l"(src));
}
__device__ __forceinline__ void ldsm4(uint32_t r[4], uint32_t a) {
    asm volatile("ldmatrix.sync.aligned.m8n8.x4.shared.b16 {%0,%1,%2,%3}, [%4];"
                 : "=r"(r[0]), "=r"(r[1]), "=r"(r[2]), "=r"(r[3]) : "r"(a));
}
__device__ __forceinline__ void ldsm4t(uint32_t r[4], uint32_t a) {
    asm volatile("ldmatrix.sync.aligned.m8n8.x4.trans.shared.b16 {%0,%1,%2,%3}, [%4];"
                 : "=r"(r[0]), "=r"(r[1]), "=r"(r[2]), "=r"(r[3]) : "r"(a));
}
__device__ __forceinline__ void mma_bf16(float d[4], const uint32_t a[4], const uint32_t b[2]) {
    asm volatile("mma.sync.aligned.m16n8k16.row.col.f32.bf16.bf16.f32 "
                 "{%0,%1,%2,%3}, {%4,%5,%6,%7}, {%8,%9}, {%0,%1,%2,%3};"
                 : "+f"(d[0]), "+f"(d[1]), "+f"(d[2]), "+f"(d[3])
                 : "r"(a[0]), "r"(a[1]), "r"(a[2]), "r"(a[3]), "r"(b[0]), "r"(b[1]));
}
__device__ __forceinline__ void mma_fp16(float d[4], const uint32_t a[4], const uint32_t b[2]) {
    asm volatile("mma.sync.aligned.m16n8k16.row.col.f32.f16.f16.f32 "
                 "{%0,%1,%2,%3}, {%4,%5,%6,%7}, {%8,%9}, {%0,%1,%2,%3};"
                 : "+f"(d[0]), "+f"(d[1]), "+f"(d[2]), "+f"(d[3])
                 : "r"(a[0]), "r"(a[1]), "r"(a[2]), "r"(a[3]), "r"(b[0]), "r"(b[1]));
}
__device__ __forceinline__ uint32_t pkbf(float x, float y) {
    uint32_t r;
    asm("cvt.rn.bf16x2.f32 %0, %1, %2;" : "=r"(r) : "f"(y), "f"(x));
    return r;
}
__device__ __forceinline__ uint32_t pk16(float x, float y) {
    uint32_t r;
    asm("cvt.rn.f16x2.f32 %0, %1, %2;" : "=r"(r) : "f"(y), "f"(x));
    return r;
}
__device__ __forceinline__ uint32_t hi2(float x, float y) {
    return __byte_perm(__float_as_uint(x), __float_as_uint(y), 0x7632);
}
__device__ __forceinline__ float hif(float x) {
    return __uint_as_float(__float_as_uint(x) & 0xffff0000u);
}
__device__ __forceinline__ float ex2(float x) {
    float y;
    asm("ex2.approx.ftz.f32 %0, %1;" : "=f"(y) : "f"(x));
    return y;
}

// ================= prologue: convert K/V/mask into swizzled tile images ==========
#define KV_ELEMS (64 * NT * 1024)
#define M_ELEMS  (16 * NT * 2048)

__global__ __launch_bounds__(256)
void prep_kernel(const float* __restrict__ K, const float* __restrict__ V,
                 const float* __restrict__ Mk)
{
    int idx = blockIdx.x * 256 + threadIdx.x;
    if (idx < KV_ELEMS) {
        int d8   = idx & 1023;          // uint2 slot in 8KB tile image
        int tile = idx >> 10;           // bh*NT + kt
        int bh = tile >> 5, kt = tile & 31;
        uint32_t u = sw((uint32_t)d8 * 8);
        int row = u >> 7;               // 0..63 (tile row)
        int c4  = (u & 127) >> 3;       // 0..15 (float4 group)
        size_t srcoff = ((size_t)bh * SEQ + (size_t)kt * BN + row) * HD + c4 * 4;
        float4 kv = *(const float4*)(K + srcoff);
        float4 vv = *(const float4*)(V + srcoff);
        g_KH[idx] = make_uint2(hi2(kv.x, kv.y), hi2(kv.z, kv.w));
        g_KL[idx] = make_uint2(pkbf(kv.x - hif(kv.x), kv.y - hif(kv.y)),
                               pkbf(kv.z - hif(kv.z), kv.w - hif(kv.w)));
        g_Vc[idx] = make_uint2(pk16(vv.x, vv.y), pk16(vv.z, vv.w));
    } else if (idx < KV_ELEMS + M_ELEMS) {
        int j    = idx - KV_ELEMS;
        int d8   = j & 2047;            // uint2 slot in 16KB tile image
        int tile = j >> 11;             // qt*NT + kt
        int qt = tile >> 5, kt = tile & 31;
        uint32_t u = sw((uint32_t)d8 * 8);
        int qrow = u >> 7;              // 0..127
        int c4   = (u & 127) >> 1;      // fp16 col base (multiple of 4)
        const float4 mv = *(const float4*)(Mk + (size_t)(qt * BM + qrow) * SEQ + kt * BN + c4);
        g_Mc[j] = make_uint2(pk16(mv.x, mv.y), pk16(mv.z, mv.w));
    }
}

// ================= main kernel ===================================================

__device__ __forceinline__ void issue_tile(uint32_t dstb, int tid,
                                           const char* sKH, const char* sKL,
                                           const char* sV, const char* sM)
{
    #pragma unroll
    for (int c = 0; c < 10; c++) {
        int byte = (c * 256 + tid) * 16;   // per-c: uniform 4KB region
        const char* src;
        if      (byte < 8192)  src = sKH + byte;
        else if (byte < 16384) src = sKL + (byte - 8192);
        else if (byte < 24576) src = sV  + (byte - 16384);
        else                   src = sM  + (byte - 24576);
        cp16(dstb + byte, src);
    }
    asm volatile("cp.async.commit_group;" ::: "memory");
}

__global__ __launch_bounds__(256, 2)
void flash_mma_kernel(const float* __restrict__ Q, float* __restrict__ O)
{
    extern __shared__ char smem[];
    const uint32_t sb = smem_u32(smem);
    const int tid  = threadIdx.x;
    const int lane = tid & 31;
    const int wid  = tid >> 5;          // 0..7, 16 Q rows per warp
    const int bh   = blockIdx.y;
    const int qt   = blockIdx.x;

    const float* Qb = Q + ((size_t)bh * SEQ + (size_t)qt * BM) * HD;
    const char* baseKH = (const char*)g_KH + ((size_t)(bh * NT) << 13);
    const char* baseKL = (const char*)g_KL + ((size_t)(bh * NT) << 13);
    const char* baseV  = (const char*)g_Vc + ((size_t)(bh * NT) << 13);
    const char* baseM  = (const char*)g_Mc + ((size_t)(qt * NT) << 14);

    const int g  = lane >> 3;
    const int i8 = lane & 7;

    // ---- issue tile 0 into stage 0 ----
    issue_tile(sb + STAGE0, tid, baseKH, baseKL, baseV, baseM);

    // ---- Load + convert Q tile (hi trunc-bf16 / lo residual) ----
    for (int j = tid; j < BM * 16; j += 256) {
        int row = j >> 4, c = j & 15;
        float4 v = *(const float4*)(Qb + row * HD + c * 4);
        uint32_t o = sw(row * 128 + c * 8);
        *(uint2*)(smem + SQHI + o) = make_uint2(hi2(v.x, v.y), hi2(v.z, v.w));
        *(uint2*)(smem + SQLO + o) =
            make_uint2(pkbf(v.x - hif(v.x), v.y - hif(v.y)),
                       pkbf(v.z - hif(v.z), v.w - hif(v.w)));
    }
    __syncthreads();

    // ---- hoist Q fragments for all 4 k-chunks ----
    uint32_t aQh[4][4], aQl[4][4];
    #pragma unroll
    for (int kc = 0; kc < 4; kc++) {
        uint32_t arow = wid * 16 + (g & 1) * 8 + i8;
        uint32_t acol = kc * 16 + (g >> 1) * 8;
        uint32_t o = sw(arow * 128 + acol * 2);
        ldsm4(aQh[kc], sb + SQHI + o);
        ldsm4(aQl[kc], sb + SQLO + o);
    }

    float Sacc[8][4];
    float Oacc[8][4];
    float mrun0 = -1e30f, mrun1 = -1e30f, lrun0 = 0.0f, lrun1 = 0.0f;
    #pragma unroll
    for (int nt = 0; nt < 8; nt++)
        #pragma unroll
        for (int e = 0; e < 4; e++) Oacc[nt][e] = 0.0f;

    const int r0 = lane >> 2;

    for (int kt = 0; kt < NT; kt++) {
        const uint32_t stg = STAGE0 + (kt & 1) * STAGEB;

        // prefetch next tile into the other stage
        if (kt < NT - 1) {
            size_t t = (size_t)(kt + 1) << 13;
            issue_tile(sb + STAGE0 + ((kt + 1) & 1) * STAGEB, tid,
                       baseKH + t, baseKL + t, baseV + t,
                       baseM + ((size_t)(kt + 1) << 14));
            asm volatile("cp.async.wait_group 1;" ::: "memory");
        } else {
            asm volatile("cp.async.wait_group 0;" ::: "memory");
        }
        __syncthreads();

        // ---- GEMM1: S = Q K^T (3-pass bf16 hi/lo) ----
        #pragma unroll
        for (int nt = 0; nt < 8; nt++)
            #pragma unroll
            for (int e = 0; e < 4; e++) Sacc[nt][e] = 0.0f;

        #pragma unroll
        for (int kc = 0; kc < 4; kc++) {
            #pragma unroll
            for (int nt2 = 0; nt2 < 4; nt2++) {
                uint32_t brow = nt2 * 16 + (g >> 1) * 8 + i8;
                uint32_t bcol = kc * 16 + (g & 1) * 8;
                uint32_t o = sw(brow * 128 + bcol * 2);
                uint32_t bKh[4], bKl[4];
                ldsm4(bKh, sb + stg + OKH + o);
                ldsm4(bKl, sb + stg + OKL + o);
                #pragma unroll
                for (int h = 0; h < 2; h++) {
                    mma_bf16(Sacc[nt2 * 2 + h], aQh[kc], bKh + 2 * h);
                    mma_bf16(Sacc[nt2 * 2 + h], aQh[kc], bKl + 2 * h);
                    mma_bf16(Sacc[nt2 * 2 + h], aQl[kc], bKh + 2 * h);
                }
            }
        }

        // ---- online softmax (mask fp16 from smem image) ----
        {
            const uint32_t mb = sb + stg + OM;
            float mx0 = -1e30f, mx1 = -1e30f;
            #pragma unroll
            for (int nt = 0; nt < 8; nt++) {
                uint32_t col = nt * 16 + (lane & 3) * 4;
                uint32_t raw0 = *(const uint32_t*)(smem + (mb - sb) + sw((wid * 16 + r0) * 128 + col));
                uint32_t raw1 = *(const uint32_t*)(smem + (mb - sb) + sw((wid * 16 + r0 + 8) * 128 + col));
                float2 m0 = __half22float2(*(const __half2*)&raw0);
                float2 m1 = __half22float2(*(const __half2*)&raw1);
                Sacc[nt][0] += m0.x;
                Sacc[nt][1] += m0.y;
                Sacc[nt][2] += m1.x;
                Sacc[nt][3] += m1.y;
                mx0 = fmaxf(mx0, fmaxf(Sacc[nt][0], Sacc[nt][1]));
                mx1 = fmaxf(mx1, fmaxf(Sacc[nt][2], Sacc[nt][3]));
            }
            mx0 = fmaxf(mx0, __shfl_xor_sync(0xffffffffu, mx0, 1));
            mx0 = fmaxf(mx0, __shfl_xor_sync(0xffffffffu, mx0, 2));
            mx1 = fmaxf(mx1, __shfl_xor_sync(0xffffffffu, mx1, 1));
            mx1 = fmaxf(mx1, __shfl_xor_sync(0xffffffffu, mx1, 2));

            float mn0 = fmaxf(mrun0, mx0);
            float mn1 = fmaxf(mrun1, mx1);
            float corr0 = ex2((mrun0 - mn0) * LOG2E);
            float corr1 = ex2((mrun1 - mn1) * LOG2E);
            mrun0 = mn0; mrun1 = mn1;

            float s0 = 0.0f, s1 = 0.0f;
            #pragma unroll
            for (int nt = 0; nt < 8; nt++) {
                float p0 = ex2((Sacc[nt][0] - mn0) * LOG2E);
                float p1 = ex2((Sacc[nt][1] - mn0) * LOG2E);
                float p2 = ex2((Sacc[nt][2] - mn1) * LOG2E);
                float p3 = ex2((Sacc[nt][3] - mn1) * LOG2E);
                s0 += p0 + p1;
                s1 += p2 + p3;
                Sacc[nt][0] = p0; Sacc[nt][1] = p1;
                Sacc[nt][2] = p2; Sacc[nt][3] = p3;
                Oacc[nt][0] *= corr0; Oacc[nt][1] *= corr0;
                Oacc[nt][2] *= corr1; Oacc[nt][3] *= corr1;
            }
            lrun0 = lrun0 * corr0 + s0;
            lrun1 = lrun1 * corr1 + s1;
        }

        // ---- GEMM2: O += P V (single-pass fp16, P from registers) ----
        #pragma unroll
        for (int kc = 0; kc < 4; kc++) {
            uint32_t aP[4];
            {
                const float* t0 = Sacc[2 * kc];
                const float* t1 = Sacc[2 * kc + 1];
                aP[0] = pk16(t0[0], t0[1]);
                aP[1] = pk16(t0[2], t0[3]);
                aP[2] = pk16(t1[0], t1[1]);
                aP[3] = pk16(t1[2], t1[3]);
            }
            #pragma unroll
            for (int nt2 = 0; nt2 < 4; nt2++) {
                uint32_t vrow = kc * 16 + (g & 1) * 8 + i8;
                uint32_t vcol = nt2 * 16 + (g >> 1) * 8;
                uint32_t o = sw(vrow * 128 + vcol * 2);
                uint32_t bV[4];
                ldsm4t(bV, sb + stg + OV + o);
                #pragma unroll
                for (int h = 0; h < 2; h++)
                    mma_fp16(Oacc[nt2 * 2 + h], aP, bV + 2 * h);
            }
        }
        __syncthreads();   // stage fully consumed before it is refilled
    }

    // ---- epilogue ----
    {
        float s0 = lrun0, s1 = lrun1;
        s0 += __shfl_xor_sync(0xffffffffu, s0, 1);
        s0 += __shfl_xor_sync(0xffffffffu, s0, 2);
        s1 += __shfl_xor_sync(0xffffffffu, s1, 1);
        s1 += __shfl_xor_sync(0xffffffffu, s1, 2);
        float inv0 = 1.0f / s0;
        float inv1 = 1.0f / s1;
        int grow = qt * BM + wid * 16 + r0;
        float* o0 = O + ((size_t)bh * SEQ + grow) * HD;
        float* o1 = O + ((size_t)bh * SEQ + grow + 8) * HD;
        #pragma unroll
        for (int nt = 0; nt < 8; nt++) {
            int c = nt * 8 + 2 * (lane & 3);
            *(float2*)(o0 + c) = make_float2(Oacc[nt][0] * inv0, Oacc[nt][1] * inv0);
            *(float2*)(o1 + c) = make_float2(Oacc[nt][2] * inv1, Oacc[nt][3] * inv1);
        }
    }
}

extern "C" void kernel_launch(void* const* d_in, const int* in_sizes, int n_in,
                              void* d_out, int out_size)
{
    const float* Q  = (const float*)d_in[0];
    const float* K  = (const float*)d_in[1];
    const float* V  = (const float*)d_in[2];
    const float* Mk = (const float*)d_in[3];
    float* O = (float*)d_out;

    int bh = in_sizes[0] / (SEQ * HD);   // B*H = 64

    prep_kernel<<<(KV_ELEMS + M_ELEMS) / 256, 256>>>(K, V, Mk);

    cudaFuncSetAttribute(flash_mma_kernel,
                         cudaFuncAttributeMaxDynamicSharedMemorySize, SMEM_TOTAL);
    dim3 grid(SEQ / BM, bh);
    flash_mma_kernel<<<grid, 256, SMEM_TOTAL>>>(Q, O);
}